// round 8
// baseline (speedup 1.0000x reference)
#include <cuda_runtime.h>

// Problem constants
#define B_  256
#define T_  1024
#define I_  3
#define H_  128
#define O_  3

#define CHUNK     32                 // steps per progress publish
#define NWORKERS  40                 // outproj worker blocks
#define GRID      (B_ + NWORKERS)    // 296 = 148 SMs x 2 blocks (all resident)

// Progress flags: recurrent block b publishes highest finished step count.
__device__ int g_progress[B_];

// ---------------------------------------------------------------------------
// Fast tanh: tanh(x) = 1 - 2/(1 + e^{2x}) via ex2.approx + rcp.approx.
// Proven end-to-end rel err ~5e-7 over the 1024-step recurrence.
// ---------------------------------------------------------------------------
__device__ __forceinline__ float fast_tanh(float x) {
    float u = fminf(x * 2.885390081777927f, 80.0f);
    float e;
    asm("ex2.approx.f32 %0, %1;" : "=f"(e) : "f"(u));
    float rd;
    asm("rcp.approx.f32 %0, %1;" : "=f"(rd) : "f"(1.0f + e));
    return fmaf(-2.0f, rd, 1.0f);
}

__device__ __forceinline__ int ld_acquire_gpu(const int* p) {
    int v;
    asm volatile("ld.acquire.gpu.b32 %0, [%1];" : "=r"(v) : "l"(p) : "memory");
    return v;
}
__device__ __forceinline__ void st_release_gpu(int* p, int v) {
    asm volatile("st.release.gpu.b32 [%0], %1;" :: "l"(p), "r"(v) : "memory");
}

// ---------------------------------------------------------------------------
// Reset kernel: zero the progress flags (stream-ordered before the main one).
// ---------------------------------------------------------------------------
__global__ void reset_kernel() {
    if (threadIdx.x < B_) g_progress[threadIdx.x] = 0;
}

// ---------------------------------------------------------------------------
// Fused kernel, two block roles:
//   blockIdx < 256 : recurrent block (R3 hot loop). Publish = ONE predicated
//                    st.release.gpu by thread 0 after the existing barrier
//                    (cumulativity makes all block stores visible). No
//                    block-wide fence.
//   blockIdx >= 256: worker block streaming the output projection of
//                    finished chunks (reads are L2-hot).
// ---------------------------------------------------------------------------
__global__ void __launch_bounds__(H_, 2)
rnn_kernel(const float* __restrict__ inputs,   // [B, T, I]
           const float* __restrict__ W_ih,     // [H, I]
           const float* __restrict__ W_hh,     // [H, H]
           const float* __restrict__ b_ih,     // [H]
           const float* __restrict__ b_hh,     // [H]
           const float* __restrict__ h0,       // [1, H]
           const float* __restrict__ W_out,    // [O, H]
           const float* __restrict__ b_out,    // [O]
           float* __restrict__ out,            // [B, T, O]
           float* __restrict__ hiddens)        // [B, T, H]
{
    if (blockIdx.x < B_) {
        // ================= recurrent block =================
        const int b = blockIdx.x;
        const int j = threadIdx.x;

        __shared__ float hbuf[2][H_];

        float w[H_];
        const float4* wrow = reinterpret_cast<const float4*>(W_hh + j * H_);
#pragma unroll
        for (int kk = 0; kk < H_ / 4; ++kk) {
            float4 v = wrow[kk];
            w[4 * kk + 0] = v.x;
            w[4 * kk + 1] = v.y;
            w[4 * kk + 2] = v.z;
            w[4 * kk + 3] = v.w;
        }

        const float wi0  = W_ih[j * I_ + 0];
        const float wi1  = W_ih[j * I_ + 1];
        const float wi2  = W_ih[j * I_ + 2];
        const float bias = b_ih[j] + b_hh[j];

        hbuf[0][j] = h0[j];
        __syncthreads();

        const float* inb  = inputs + (size_t)b * T_ * I_;
        float*       hout = hiddens + (size_t)b * T_ * H_;

        float x0 = inb[0], x1 = inb[1], x2 = inb[2];

        int cur = 0;
#pragma unroll 1
        for (int t = 0; t < T_; ++t) {
            float acc = fmaf(x0, wi0, fmaf(x1, wi1, fmaf(x2, wi2, bias)));

            {
                const int tn = (t + 1 < T_) ? (t + 1) : (T_ - 1);
                const float* nx = inb + tn * I_;
                x0 = nx[0]; x1 = nx[1]; x2 = nx[2];
            }

            float a0 = 0.f, a1 = 0.f, a2 = 0.f, a3 = 0.f;
            const float4* h4 = reinterpret_cast<const float4*>(hbuf[cur]);
#pragma unroll
            for (int kk = 0; kk < H_ / 4; ++kk) {
                float4 hv = h4[kk];
                a0 = fmaf(hv.x, w[4 * kk + 0], a0);
                a1 = fmaf(hv.y, w[4 * kk + 1], a1);
                a2 = fmaf(hv.z, w[4 * kk + 2], a2);
                a3 = fmaf(hv.w, w[4 * kk + 3], a3);
            }
            acc += (a0 + a1) + (a2 + a3);

            const float hn = fast_tanh(acc);
            const int nxt = cur ^ 1;
            hbuf[nxt][j] = hn;
            hout[t * H_ + j] = hn;
            cur = nxt;
            __syncthreads();

            // Publish progress: barrier ordered all hout stores for steps
            // <= t before this point; the release is cumulative, so one
            // store by thread 0 makes them visible to acquiring workers.
            if (((t + 1) & (CHUNK - 1)) == 0 && j == 0)
                st_release_gpu(&g_progress[b], t + 1);
        }
    } else {
        // ================= worker block: streamed output projection =========
        const int w    = blockIdx.x - B_;    // 0..39
        const int tid  = threadIdx.x;
        const int lane = tid & 31;
        const int warp = tid >> 5;

        const float4 w0 = reinterpret_cast<const float4*>(W_out + 0 * H_)[lane];
        const float4 w1 = reinterpret_cast<const float4*>(W_out + 1 * H_)[lane];
        const float4 w2 = reinterpret_cast<const float4*>(W_out + 2 * H_)[lane];
        const float bo0 = b_out[0], bo1 = b_out[1], bo2 = b_out[2];

#pragma unroll 1
        for (int c = 0; c < T_ / CHUNK; ++c) {
            const int t0     = c * CHUNK;
            const int target = t0 + CHUNK;
#pragma unroll 1
            for (int b = w; b < B_; b += NWORKERS) {
                while (ld_acquire_gpu(&g_progress[b]) < target)
                    __nanosleep(300);

                // 32 rows: each warp handles 8 (two groups of 4)
#pragma unroll 1
                for (int g = 0; g < 2; ++g) {
                    const size_t rowbase = (size_t)b * T_ + t0 + warp * 8 + g * 4;

                    float4 hv[4];
#pragma unroll
                    for (int r = 0; r < 4; ++r)
                        hv[r] = reinterpret_cast<const float4*>(
                                    hiddens + (rowbase + r) * H_)[lane];

#pragma unroll
                    for (int r = 0; r < 4; ++r) {
                        float s0 = hv[r].x * w0.x + hv[r].y * w0.y + hv[r].z * w0.z + hv[r].w * w0.w;
                        float s1 = hv[r].x * w1.x + hv[r].y * w1.y + hv[r].z * w1.z + hv[r].w * w1.w;
                        float s2 = hv[r].x * w2.x + hv[r].y * w2.y + hv[r].z * w2.z + hv[r].w * w2.w;
#pragma unroll
                        for (int off = 16; off > 0; off >>= 1) {
                            s0 += __shfl_down_sync(0xffffffffu, s0, off);
                            s1 += __shfl_down_sync(0xffffffffu, s1, off);
                            s2 += __shfl_down_sync(0xffffffffu, s2, off);
                        }
                        if (lane == 0) {
                            float* o = out + (rowbase + r) * O_;
                            o[0] = s0 + bo0;
                            o[1] = s1 + bo1;
                            o[2] = s2 + bo2;
                        }
                    }
                }
            }
        }
    }
}

// ---------------------------------------------------------------------------
// kernel_launch
// ---------------------------------------------------------------------------
extern "C" void kernel_launch(void* const* d_in, const int* in_sizes, int n_in,
                              void* d_out, int out_size)
{
    const float* inputs = (const float*)d_in[0];
    const float* W_ih   = (const float*)d_in[1];
    const float* W_hh   = (const float*)d_in[2];
    const float* b_ih   = (const float*)d_in[3];
    const float* b_hh   = (const float*)d_in[4];
    const float* h0     = (const float*)d_in[5];
    const float* W_out  = (const float*)d_in[6];
    const float* b_out  = (const float*)d_in[7];

    float* out     = (float*)d_out;                        // [B,T,O]
    float* hiddens = (float*)d_out + (size_t)B_ * T_ * O_; // [B,T,H]

    reset_kernel<<<1, 256>>>();
    rnn_kernel<<<GRID, H_>>>(inputs, W_ih, W_hh, b_ih, b_hh, h0,
                             W_out, b_out, out, hiddens);
}

// round 9
// speedup vs baseline: 1.1610x; 1.1610x over previous
#include <cuda_runtime.h>

// Problem constants
#define B_  256
#define T_  1024
#define I_  3
#define H_  128
#define O_  3

// ---------------------------------------------------------------------------
// Fast tanh: tanh(x) = 1 - 2/(1 + e^{2x}) via ex2.approx + rcp.approx.
// Proven end-to-end rel err ~5e-7 over the 1024-step recurrence.
// ---------------------------------------------------------------------------
__device__ __forceinline__ float fast_tanh(float x) {
    float u = fminf(x * 2.885390081777927f, 80.0f);
    float e;
    asm("ex2.approx.f32 %0, %1;" : "=f"(e) : "f"(u));
    float rd;
    asm("rcp.approx.f32 %0, %1;" : "=f"(rd) : "f"(1.0f + e));
    return fmaf(-2.0f, rd, 1.0f);
}

// ---------------------------------------------------------------------------
// Recurrent kernel + self-epilogue output projection.
// Phase 1 (identical to the proven R3 hot loop): one block per batch, one
// thread per hidden unit, W_hh row in 128 registers, double-buffered h in
// smem, one barrier per step, fused input projection with x prefetch.
// Phase 2: after the block finishes its recurrence, it projects its OWN
// batch's hiddens (just written -> L2-hot) against W_out. W_out is loaded
// after the loop so the hot loop's register allocation is untouched
// (w[] is dead by then; the allocator reuses those registers).
// ---------------------------------------------------------------------------
__global__ void __launch_bounds__(H_, 2)
rnn_kernel(const float* __restrict__ inputs,   // [B, T, I]
           const float* __restrict__ W_ih,     // [H, I]
           const float* __restrict__ W_hh,     // [H, H]
           const float* __restrict__ b_ih,     // [H]
           const float* __restrict__ b_hh,     // [H]
           const float* __restrict__ h0,       // [1, H]
           const float* __restrict__ W_out,    // [O, H]
           const float* __restrict__ b_out,    // [O]
           float* __restrict__ out,            // [B, T, O]
           float* __restrict__ hiddens)        // [B, T, H]
{
    const int b = blockIdx.x;
    const int j = threadIdx.x;

    __shared__ float hbuf[2][H_];

    // ---------------- Phase 1: recurrence (R3 core) ----------------
    {
        float w[H_];
        const float4* wrow = reinterpret_cast<const float4*>(W_hh + j * H_);
#pragma unroll
        for (int kk = 0; kk < H_ / 4; ++kk) {
            float4 v = wrow[kk];
            w[4 * kk + 0] = v.x;
            w[4 * kk + 1] = v.y;
            w[4 * kk + 2] = v.z;
            w[4 * kk + 3] = v.w;
        }

        const float wi0  = W_ih[j * I_ + 0];
        const float wi1  = W_ih[j * I_ + 1];
        const float wi2  = W_ih[j * I_ + 2];
        const float bias = b_ih[j] + b_hh[j];

        hbuf[0][j] = h0[j];
        __syncthreads();

        const float* inb  = inputs + (size_t)b * T_ * I_;
        float*       hout = hiddens + (size_t)b * T_ * H_;

        float x0 = inb[0], x1 = inb[1], x2 = inb[2];

        int cur = 0;
#pragma unroll 1
        for (int t = 0; t < T_; ++t) {
            float acc = fmaf(x0, wi0, fmaf(x1, wi1, fmaf(x2, wi2, bias)));

            // prefetch next x (off the critical tail)
            {
                const int tn = (t + 1 < T_) ? (t + 1) : (T_ - 1);
                const float* nx = inb + tn * I_;
                x0 = nx[0]; x1 = nx[1]; x2 = nx[2];
            }

            float a0 = 0.f, a1 = 0.f, a2 = 0.f, a3 = 0.f;
            const float4* h4 = reinterpret_cast<const float4*>(hbuf[cur]);
#pragma unroll
            for (int kk = 0; kk < H_ / 4; ++kk) {
                float4 hv = h4[kk];
                a0 = fmaf(hv.x, w[4 * kk + 0], a0);
                a1 = fmaf(hv.y, w[4 * kk + 1], a1);
                a2 = fmaf(hv.z, w[4 * kk + 2], a2);
                a3 = fmaf(hv.w, w[4 * kk + 3], a3);
            }
            acc += (a0 + a1) + (a2 + a3);

            const float hn = fast_tanh(acc);
            const int nxt = cur ^ 1;
            hbuf[nxt][j] = hn;
            hout[t * H_ + j] = hn;
            cur = nxt;
            __syncthreads();
        }
    }

    // ---------------- Phase 2: self-epilogue output projection ----------------
    // This block projects its own batch: 1024 rows, 4 warps, 4-row groups.
    {
        const int lane = j & 31;
        const int warp = j >> 5;

        const float4 w0 = reinterpret_cast<const float4*>(W_out + 0 * H_)[lane];
        const float4 w1 = reinterpret_cast<const float4*>(W_out + 1 * H_)[lane];
        const float4 w2 = reinterpret_cast<const float4*>(W_out + 2 * H_)[lane];
        const float bo0 = b_out[0], bo1 = b_out[1], bo2 = b_out[2];

        const float* hb = hiddens + (size_t)b * T_ * H_;
        float*       ob = out + (size_t)b * T_ * O_;

        // warp handles rows [warp*4 + g*16 .. +3] stepped by 64
#pragma unroll 1
        for (int base = warp * 4; base < T_; base += 16) {
            float4 hv[4];
#pragma unroll
            for (int r = 0; r < 4; ++r)
                hv[r] = reinterpret_cast<const float4*>(hb + (size_t)(base + r) * H_)[lane];

#pragma unroll
            for (int r = 0; r < 4; ++r) {
                float s0 = hv[r].x * w0.x + hv[r].y * w0.y + hv[r].z * w0.z + hv[r].w * w0.w;
                float s1 = hv[r].x * w1.x + hv[r].y * w1.y + hv[r].z * w1.z + hv[r].w * w1.w;
                float s2 = hv[r].x * w2.x + hv[r].y * w2.y + hv[r].z * w2.z + hv[r].w * w2.w;
#pragma unroll
                for (int off = 16; off > 0; off >>= 1) {
                    s0 += __shfl_down_sync(0xffffffffu, s0, off);
                    s1 += __shfl_down_sync(0xffffffffu, s1, off);
                    s2 += __shfl_down_sync(0xffffffffu, s2, off);
                }
                if (lane == 0) {
                    float* o = ob + (size_t)(base + r) * O_;
                    o[0] = s0 + bo0;
                    o[1] = s1 + bo1;
                    o[2] = s2 + bo2;
                }
            }
        }
    }
}

// ---------------------------------------------------------------------------
// kernel_launch
// ---------------------------------------------------------------------------
extern "C" void kernel_launch(void* const* d_in, const int* in_sizes, int n_in,
                              void* d_out, int out_size)
{
    const float* inputs = (const float*)d_in[0];
    const float* W_ih   = (const float*)d_in[1];
    const float* W_hh   = (const float*)d_in[2];
    const float* b_ih   = (const float*)d_in[3];
    const float* b_hh   = (const float*)d_in[4];
    const float* h0     = (const float*)d_in[5];
    const float* W_out  = (const float*)d_in[6];
    const float* b_out  = (const float*)d_in[7];

    float* out     = (float*)d_out;                        // [B,T,O]
    float* hiddens = (float*)d_out + (size_t)B_ * T_ * O_; // [B,T,H]

    rnn_kernel<<<B_, H_>>>(inputs, W_ih, W_hh, b_ih, b_hh, h0,
                           W_out, b_out, out, hiddens);
}